// round 16
// baseline (speedup 1.0000x reference)
#include <cuda_runtime.h>
#include <cuda_fp16.h>
#include <cstdint>
#include <math.h>

typedef __half f16;

// ---------------- problem dims ----------------
#define Bn 64
#define Nn 256
#define Fn 16
#define Hn 256
#define ROWS (Bn*Nn)          // 16384
#define N_ITERS 10
#define PLANE (ROWS*Hn)       // 4194304

// ---------------- scratch ----------------
__device__ float g_h  [PLANE];
__device__ float g_z  [PLANE];
__device__ float g_jcz[PLANE];
__device__ float g_jcr[PLANE];
__device__ float g_jch[PLANE];
__device__ float g_t1 [PLANE];
__device__ float g_s  [Bn*Hn];
__device__ f16 g_hP [PLANE];
__device__ f16 g_tP [PLANE];
__device__ f16 g_mP [PLANE];
__device__ f16 g_rhP[PLANE];
__device__ f16 g_daP[PLANE];
#define WOFF_MSG 0
#define WOFF_ZR  65536
#define WOFF_HB  327680
#define WOFF_R1  458752
#define WTOTAL   524288
__device__ f16 g_wH[WTOTAL];

__device__ __forceinline__ float sigf(float x) { return 1.0f / (1.0f + expf(-x)); }

__device__ __forceinline__ uint32_t smem_u32(const void* p) {
    return (uint32_t)__cvta_generic_to_shared(p);
}
#define CP16(dst, src) asm volatile("cp.async.cg.shared.global [%0], [%1], 16;" :: "r"(dst), "l"(src))
#define CP_COMMIT()    asm volatile("cp.async.commit_group;" ::: "memory")
#define CP_WAIT(n)     asm volatile("cp.async.wait_group %0;" :: "n"(n) : "memory")
#define GDC_WAIT()     asm volatile("griddepcontrol.wait;" ::: "memory")
#define GDC_LAUNCH()   asm volatile("griddepcontrol.launch_dependents;")

__device__ __forceinline__ void store_hi2(f16* Ph, size_t idx, float2 v) {
    __half2 h = __floats2half2_rn(v.x, v.y);
    *(uint32_t*)(Ph + idx) = *(uint32_t*)&h;
}

// ---------------- raw mma helpers ----------------
__device__ __forceinline__ void ldsm4(uint32_t addr, uint32_t& r0, uint32_t& r1, uint32_t& r2, uint32_t& r3) {
    asm volatile("ldmatrix.sync.aligned.m8n8.x4.shared.b16 {%0,%1,%2,%3}, [%4];"
                 : "=r"(r0), "=r"(r1), "=r"(r2), "=r"(r3) : "r"(addr));
}
__device__ __forceinline__ void ldsm4t(uint32_t addr, uint32_t& r0, uint32_t& r1, uint32_t& r2, uint32_t& r3) {
    asm volatile("ldmatrix.sync.aligned.m8n8.x4.trans.shared.b16 {%0,%1,%2,%3}, [%4];"
                 : "=r"(r0), "=r"(r1), "=r"(r2), "=r"(r3) : "r"(addr));
}
__device__ __forceinline__ void mma16816(float* d, const uint32_t* a, const uint32_t* b) {
    asm volatile("mma.sync.aligned.m16n8k16.row.col.f32.f16.f16.f32 "
                 "{%0,%1,%2,%3}, {%4,%5,%6,%7}, {%8,%9}, {%0,%1,%2,%3};"
                 : "+f"(d[0]), "+f"(d[1]), "+f"(d[2]), "+f"(d[3])
                 : "r"(a[0]), "r"(a[1]), "r"(a[2]), "r"(a[3]), "r"(b[0]), "r"(b[1]));
}

// ---------------- GEMM: 128x128 tile, fp16, 4-stage cp.async, PDL ------
enum { EPI_T = 0, EPI_M, EPI_ZR, EPI_GRU, EPI_R1 };

#define STAGES 4
#define LDA 40
#define LDB 136
#define A_OFF 0
#define B_OFF 10240
#define STAGE_BYTES 18944
#define SMEM_BYTES (STAGES*STAGE_BYTES)   // 75776 (x2 CTA/SM = 151552 <= 228KB)

template<int EPI, bool PRE_A, bool PRE_B>
__global__ void __launch_bounds__(256, 2)
tc_gemm(const f16* __restrict__ A0, const f16* __restrict__ A1,
        const f16* __restrict__ B,
        int NB, int K, int batched,
        const float* __restrict__ bias,
        const float* __restrict__ jc,  const float* __restrict__ jc2,
        const float* __restrict__ Hb,  const float* __restrict__ Zb,
        float* Cf, f16* Ch)
{
    extern __shared__ char sm[];
    const uint32_t smaddr = smem_u32(sm);

    const int tid = threadIdx.x, wid = tid >> 5, lane = tid & 31;
    const int bn = blockIdx.x * 128, bm = blockIdx.y * 128;
    const int warp_m = wid >> 2;
    const int warp_n = wid & 3;

    int am = bm;
    size_t aoff = 0, boff = 0;
    if (batched) {
        const int b = bm >> 8;
        aoff = (size_t)b * (Nn * Hn);
        boff = (size_t)b * (Nn * Hn);
        am = bm & (Nn - 1);
    }

    const int NC = K >> 5;

    auto issueA = [&](int kb) {
        const uint32_t sb = smaddr + (kb % STAGES) * STAGE_BYTES;
        const int kk = (kb & 7) * 32;
        const f16* ap; int arow;
        if (kb < 8) { ap = A0 + aoff; arow = am; }
        else        { ap = A1;        arow = bm; }
        #pragma unroll
        for (int i = 0; i < 2; i++) {
            const int c = tid + i * 256;
            const int r = c >> 2, c8 = (c & 3) * 8;
            CP16(sb + A_OFF + (uint32_t)(r * LDA + c8) * 2,
                 ap + (size_t)(arow + r) * Hn + kk + c8);
        }
    };
    auto issueB = [&](int kb) {
        const uint32_t sb = smaddr + (kb % STAGES) * STAGE_BYTES;
        #pragma unroll
        for (int i = 0; i < 2; i++) {
            const int c = tid + i * 256;
            const int r = c >> 4, c8 = (c & 15) * 8;
            CP16(sb + B_OFF + (uint32_t)(r * LDB + c8) * 2,
                 B + boff + (size_t)(kb * 32 + r) * NB + bn + c8);
        }
    };

    float acc[4][4][4];
    #pragma unroll
    for (int mi = 0; mi < 4; mi++)
        #pragma unroll
        for (int nj = 0; nj < 4; nj++)
            #pragma unroll
            for (int q = 0; q < 4; q++) acc[mi][nj][q] = 0.0f;

    const uint32_t a_lrow = (uint32_t)(lane & 15);
    const uint32_t a_lcol = (uint32_t)((lane >> 4) << 3);

    // -------- PDL-aware 4-stage prologue: chunks 0..S-2 --------
    if (PRE_A) { issueA(0); issueA(1); issueA(2); }
    if (PRE_B) { issueB(0); issueB(1); issueB(2); }
    CP_COMMIT();                        // group P (pre-wait loads; may be empty)
    GDC_WAIT();
    GDC_LAUNCH();
    #pragma unroll
    for (int c = 0; c < STAGES - 1; c++) {
        if (!PRE_A) issueA(c);
        if (!PRE_B) issueB(c);
        CP_COMMIT();                    // groups g0..g2
    }

    for (int kb = 0; kb < NC; kb++) {
        CP_WAIT(2);                     // chunk kb fully landed
        __syncthreads();                // all warps done with buf (kb-1)%S

        if (kb + STAGES - 1 < NC) { issueA(kb + STAGES - 1); issueB(kb + STAGES - 1); }
        CP_COMMIT();

        const uint32_t sb = smaddr + (kb % STAGES) * STAGE_BYTES;

        #pragma unroll
        for (int kk = 0; kk < 2; kk++) {
            const uint32_t brow = (uint32_t)(kk * 16) + a_lrow;
            const uint32_t bcol0 = (uint32_t)(warp_n * 32) + a_lcol;
            uint32_t bfr[8];
            {
                const uint32_t ba = sb + B_OFF + (brow * LDB + bcol0) * 2;
                ldsm4t(ba,      bfr[0], bfr[1], bfr[2], bfr[3]);
                ldsm4t(ba + 32, bfr[4], bfr[5], bfr[6], bfr[7]);
            }
            const uint32_t arow0 = (uint32_t)(warp_m * 64) + a_lrow;
            const uint32_t acol = (uint32_t)(kk * 16) + a_lcol;
            #pragma unroll
            for (int mi = 0; mi < 4; mi++) {
                uint32_t a[4];
                ldsm4(sb + A_OFF + ((arow0 + mi * 16) * LDA + acol) * 2, a[0], a[1], a[2], a[3]);
                #pragma unroll
                for (int nj = 0; nj < 4; nj++) mma16816(acc[mi][nj], a, &bfr[nj * 2]);
            }
        }
    }

    // ---------------- register-direct epilogue ----------------
    const int r_in = lane >> 2;
    const int c_in = (lane & 3) * 2;

    #pragma unroll
    for (int mi = 0; mi < 4; mi++) {
        #pragma unroll
        for (int nj = 0; nj < 4; nj++) {
            #pragma unroll
            for (int half = 0; half < 2; half++) {
                const int row = bm + warp_m * 64 + mi * 16 + r_in + half * 8;
                const int col = bn + warp_n * 32 + nj * 8 + c_in;
                float2 v = make_float2(acc[mi][nj][half * 2], acc[mi][nj][half * 2 + 1]);

                if (EPI == EPI_T) {
                    const size_t idx = (size_t)row * Hn + col;
                    float2 bv = *(const float2*)(bias + col);
                    v.x += bv.x; v.y += bv.y;
                    store_hi2(Ch, idx, v);
                } else if (EPI == EPI_M) {
                    const size_t idx = (size_t)row * Hn + col;
                    v.x = tanhf(v.x); v.y = tanhf(v.y);
                    store_hi2(Ch, idx, v);
                } else if (EPI == EPI_ZR) {
                    if (col < 256) {                      // z half
                        const size_t idx = (size_t)row * Hn + col;
                        float2 jv = *(const float2*)(jc + idx);
                        v.x = sigf(v.x + jv.x); v.y = sigf(v.y + jv.y);
                        *(float2*)(Cf + idx) = v;
                    } else {                              // rh half
                        const size_t idx = (size_t)row * Hn + (col - 256);
                        float2 jv = *(const float2*)(jc2 + idx);
                        float2 hv = *(const float2*)(Hb + idx);
                        v.x = sigf(v.x + jv.x) * hv.x;
                        v.y = sigf(v.y + jv.y) * hv.y;
                        store_hi2(Ch, idx, v);
                    }
                } else if (EPI == EPI_GRU) {
                    const size_t idx = (size_t)row * Hn + col;
                    float2 jv = *(const float2*)(jc + idx);
                    float2 hv = *(const float2*)(Hb + idx);
                    float2 zv = *(const float2*)(Zb + idx);
                    float t0 = tanhf(v.x + jv.x), t1 = tanhf(v.y + jv.y);
                    v.x = hv.x + zv.x * (t0 - hv.x);
                    v.y = hv.y + zv.y * (t1 - hv.y);
                    *(float2*)(Cf + idx) = v;
                    store_hi2(Ch, idx, v);
                } else if (EPI == EPI_R1) {
                    const size_t idx = (size_t)row * Hn + col;
                    float2 bv = *(const float2*)(bias + col);
                    v.x = tanhf(v.x + bv.x); v.y = tanhf(v.y + bv.y);
                    *(float2*)(Cf + idx) = v;
                }
            }
        }
    }
}

// ---------------- prep kernels ----------------
__global__ void cvt_hi(const float* __restrict__ src, int n4, f16* __restrict__ hi)
{
    const int i = blockIdx.x * 256 + threadIdx.x;
    if (i < n4) {
        float4 v = *(const float4*)(src + i * 4);
        __half2 h01 = __floats2half2_rn(v.x, v.y);
        __half2 h23 = __floats2half2_rn(v.z, v.w);
        uint2 hv; hv.x = *(uint32_t*)&h01; hv.y = *(uint32_t*)&h23;
        *(uint2*)(hi + (size_t)i * 4) = hv;
    }
}

__global__ void build_zrB(const float* __restrict__ Wz, const float* __restrict__ Wr,
                          const float* __restrict__ Uz, const float* __restrict__ Ur,
                          f16* __restrict__ hi)
{
    const int i = blockIdx.x * 256 + threadIdx.x;
    const int k = i >> 9, c = i & 511;
    float v;
    if (k < 256) v = (c < 256) ? Wz[k * Hn + c] : Wr[k * Hn + (c - 256)];
    else         v = (c < 256) ? Uz[(k - 256) * Hn + c] : Ur[(k - 256) * Hn + (c - 256)];
    hi[i] = __float2half_rn(v);
}

__global__ void build_hB(const float* __restrict__ Wh, const float* __restrict__ Uh,
                         f16* __restrict__ hi)
{
    const int i = blockIdx.x * 256 + threadIdx.x;
    const int k = i >> 8, c = i & 255;
    float v = (k < 256) ? Wh[k * Hn + c] : Uh[(k - 256) * Hn + c];
    hi[i] = __float2half_rn(v);
}

__global__ void emb_kernel(const float* __restrict__ jets, const float* __restrict__ W_emb,
                           const float* __restrict__ b_emb, float* __restrict__ h,
                           f16* __restrict__ hPh)
{
    const int row = blockIdx.x, j = threadIdx.x;
    __shared__ float sj[Fn];
    if (j < Fn) sj[j] = jets[(size_t)row * Fn + j];
    __syncthreads();
    float acc = b_emb[j];
    #pragma unroll
    for (int k = 0; k < Fn; k++) acc = fmaf(sj[k], W_emb[k * Hn + j], acc);
    const float v = tanhf(acc);
    const size_t idx = (size_t)row * Hn + j;
    h[idx] = v;
    hPh[idx] = __float2half_rn(v);
}

__global__ void jc_kernel(const float* __restrict__ jets,
                          const float* __restrict__ Wz, const float* __restrict__ Wr,
                          const float* __restrict__ Wh,
                          const float* __restrict__ bz, const float* __restrict__ br,
                          const float* __restrict__ bh,
                          float* jcz, float* jcr, float* jch)
{
    const int row = blockIdx.x, j = threadIdx.x;
    __shared__ float sj[Fn];
    if (j < Fn) sj[j] = jets[(size_t)row * Fn + j];
    __syncthreads();
    float az = bz[j], ar = br[j], ah = bh[j];
    #pragma unroll
    for (int k = 0; k < Fn; k++) {
        const float s = sj[k];
        const int widx = (Hn + k) * Hn + j;
        az = fmaf(s, Wz[widx], az);
        ar = fmaf(s, Wr[widx], ar);
        ah = fmaf(s, Wh[widx], ah);
    }
    const size_t idx = (size_t)row * Hn + j;
    jcz[idx] = az; jcr[idx] = ar; jch[idx] = ah;
}

__global__ void reduce_kernel(const float* __restrict__ t1, float* __restrict__ s)
{
    const int idx = blockIdx.x * blockDim.x + threadIdx.x;
    const int b = idx >> 8, j = idx & 255;
    const float* p = t1 + (size_t)b * (Nn * Hn) + j;
    float acc = 0.0f;
    for (int n = 0; n < Nn; n++) acc += p[(size_t)n * Hn];
    s[idx] = acc;
}

__global__ void readout_kernel(const float* __restrict__ s, const float* __restrict__ W_r2,
                               const float* __restrict__ b_r2, float* __restrict__ out)
{
    const int b = blockIdx.x, j = threadIdx.x;
    __shared__ float sr[Hn];
    sr[j] = s[(size_t)b * Hn + j];
    __syncthreads();
    float acc = (float)Nn * b_r2[j];
    #pragma unroll 8
    for (int k = 0; k < Hn; k++)
        acc = fmaf(sr[k], W_r2[k * Hn + j], acc);
    out[(size_t)b * Hn + j] = acc;
}

// ---------------- launch ----------------
template<typename KF, typename... Args>
static inline void pdl_launch(KF kern, dim3 grid, Args... args)
{
    cudaLaunchConfig_t cfg = {};
    cfg.gridDim = grid;
    cfg.blockDim = dim3(256, 1, 1);
    cfg.dynamicSmemBytes = SMEM_BYTES;
    cfg.stream = 0;
    cudaLaunchAttribute at[1];
    at[0].id = cudaLaunchAttributeProgrammaticStreamSerialization;
    at[0].val.programmaticStreamSerializationAllowed = 1;
    cfg.attrs = at;
    cfg.numAttrs = 1;
    cudaLaunchKernelEx(&cfg, kern, args...);
}

extern "C" void kernel_launch(void* const* d_in, const int* in_sizes, int n_in,
                              void* d_out, int out_size)
{
    const float* jets  = (const float*)d_in[0];
    const float* dads  = (const float*)d_in[1];
    const float* W_emb = (const float*)d_in[2];
    const float* b_emb = (const float*)d_in[3];
    const float* W_msg = (const float*)d_in[4];
    const float* b_msg = (const float*)d_in[5];
    const float* Wz    = (const float*)d_in[6];
    const float* Uz    = (const float*)d_in[7];
    const float* bz    = (const float*)d_in[8];
    const float* Wr    = (const float*)d_in[9];
    const float* Ur    = (const float*)d_in[10];
    const float* br    = (const float*)d_in[11];
    const float* Wh    = (const float*)d_in[12];
    const float* Uh    = (const float*)d_in[13];
    const float* bh    = (const float*)d_in[14];
    const float* W_r1  = (const float*)d_in[15];
    const float* b_r1  = (const float*)d_in[16];
    const float* W_r2  = (const float*)d_in[17];
    const float* b_r2  = (const float*)d_in[18];
    float* out = (float*)d_out;

    float *h, *z, *jcz, *jcr, *jch, *t1, *s;
    f16 *hP, *tP, *mP, *rhP, *daP, *wH;
    cudaGetSymbolAddress((void**)&h,   g_h);
    cudaGetSymbolAddress((void**)&z,   g_z);
    cudaGetSymbolAddress((void**)&jcz, g_jcz);
    cudaGetSymbolAddress((void**)&jcr, g_jcr);
    cudaGetSymbolAddress((void**)&jch, g_jch);
    cudaGetSymbolAddress((void**)&t1,  g_t1);
    cudaGetSymbolAddress((void**)&s,   g_s);
    cudaGetSymbolAddress((void**)&hP,  g_hP);
    cudaGetSymbolAddress((void**)&tP,  g_tP);
    cudaGetSymbolAddress((void**)&mP,  g_mP);
    cudaGetSymbolAddress((void**)&rhP, g_rhP);
    cudaGetSymbolAddress((void**)&daP, g_daP);
    cudaGetSymbolAddress((void**)&wH,  g_wH);

    static bool attr_done = false;
    if (!attr_done) {
        cudaFuncSetAttribute(tc_gemm<EPI_T,false,true>,  cudaFuncAttributeMaxDynamicSharedMemorySize, SMEM_BYTES);
        cudaFuncSetAttribute(tc_gemm<EPI_M,true,false>,  cudaFuncAttributeMaxDynamicSharedMemorySize, SMEM_BYTES);
        cudaFuncSetAttribute(tc_gemm<EPI_ZR,false,true>, cudaFuncAttributeMaxDynamicSharedMemorySize, SMEM_BYTES);
        cudaFuncSetAttribute(tc_gemm<EPI_GRU,true,true>, cudaFuncAttributeMaxDynamicSharedMemorySize, SMEM_BYTES);
        cudaFuncSetAttribute(tc_gemm<EPI_R1,false,true>, cudaFuncAttributeMaxDynamicSharedMemorySize, SMEM_BYTES);
        attr_done = true;
    }

    // prep
    cvt_hi<<<PLANE/4/256, 256>>>(dads, PLANE/4, daP);
    cvt_hi<<<65536/4/256, 256>>>(W_msg, 65536/4, wH + WOFF_MSG);
    cvt_hi<<<65536/4/256, 256>>>(W_r1,  65536/4, wH + WOFF_R1);
    build_zrB<<<262144/256, 256>>>(Wz, Wr, Uz, Ur, wH + WOFF_ZR);
    build_hB<<<131072/256, 256>>>(Wh, Uh, wH + WOFF_HB);
    emb_kernel<<<ROWS, Hn>>>(jets, W_emb, b_emb, h, hP);
    jc_kernel<<<ROWS, Hn>>>(jets, Wz, Wr, Wh, bz, br, bh, jcz, jcr, jch);

    dim3 grid2(2, ROWS/128);   // 256 CTAs
    dim3 grid4(4, ROWS/128);   // 512 CTAs (ZR fused)
    for (int it = 0; it < N_ITERS; it++) {
        // t = h @ W_msg + b_msg
        pdl_launch(tc_gemm<EPI_T,false,true>, grid2,
            hP, (const f16*)nullptr, (const f16*)(wH + WOFF_MSG), 256, 256, 0,
            b_msg, (const float*)nullptr, (const float*)nullptr, (const float*)nullptr,
            (const float*)nullptr, (float*)nullptr, tP);
        // m = tanh(dads @ t)
        pdl_launch(tc_gemm<EPI_M,true,false>, grid2,
            daP, (const f16*)nullptr, tP, 256, 256, 1,
            (const float*)nullptr, (const float*)nullptr, (const float*)nullptr,
            (const float*)nullptr, (const float*)nullptr, (float*)nullptr, mP);
        // [z|rh] = gates([m|h] @ zrB)  (fused, N=512)
        pdl_launch(tc_gemm<EPI_ZR,false,true>, grid4,
            mP, hP, (const f16*)(wH + WOFF_ZR), 512, 512, 0,
            (const float*)nullptr, jcz, jcr, h, (const float*)nullptr,
            z, rhP);
        // h = (1-z)*h + z*tanh([m|rh] @ hB + jch)
        pdl_launch(tc_gemm<EPI_GRU,true,true>, grid2,
            mP, rhP, (const f16*)(wH + WOFF_HB), 256, 512, 0,
            (const float*)nullptr, jch, (const float*)nullptr, h, z,
            h, hP);
    }

    // readout
    pdl_launch(tc_gemm<EPI_R1,false,true>, grid2,
        hP, (const f16*)nullptr, (const f16*)(wH + WOFF_R1), 256, 256, 0,
        b_r1, (const float*)nullptr, (const float*)nullptr, (const float*)nullptr,
        (const float*)nullptr, t1, (f16*)nullptr);
    reduce_kernel<<<ROWS/256, 256>>>(t1, s);
    readout_kernel<<<Bn, Hn>>>(s, W_r2, b_r2, out);
}

// round 17
// speedup vs baseline: 1.0305x; 1.0305x over previous
#include <cuda_runtime.h>
#include <cuda_fp16.h>
#include <cstdint>
#include <math.h>

typedef __half f16;

// ---------------- problem dims ----------------
#define Bn 64
#define Nn 256
#define Fn 16
#define Hn 256
#define ROWS (Bn*Nn)          // 16384
#define N_ITERS 10
#define PLANE (ROWS*Hn)       // 4194304

// ---------------- scratch ----------------
__device__ float g_h  [PLANE];
__device__ float g_z  [PLANE];
__device__ float g_jcz[PLANE];
__device__ float g_jcr[PLANE];
__device__ float g_jch[PLANE];
__device__ float g_t1 [PLANE];
__device__ float g_s  [Bn*Hn];
__device__ f16 g_hP [PLANE];
__device__ f16 g_tP [PLANE];
__device__ f16 g_mP [PLANE];
__device__ f16 g_rhP[PLANE];
__device__ f16 g_daP[PLANE];
#define WOFF_MSG 0
#define WOFF_ZR  65536
#define WOFF_HB  327680
#define WOFF_R1  458752
#define WTOTAL   524288
__device__ f16 g_wH[WTOTAL];

__device__ __forceinline__ float sigf(float x) { return 1.0f / (1.0f + expf(-x)); }

__device__ __forceinline__ uint32_t smem_u32(const void* p) {
    return (uint32_t)__cvta_generic_to_shared(p);
}
#define CP16(dst, src) asm volatile("cp.async.cg.shared.global [%0], [%1], 16;" :: "r"(dst), "l"(src))
#define CP_COMMIT()    asm volatile("cp.async.commit_group;" ::: "memory")
#define CP_WAIT(n)     asm volatile("cp.async.wait_group %0;" :: "n"(n) : "memory")
#define GDC_WAIT()     asm volatile("griddepcontrol.wait;" ::: "memory")
#define GDC_LAUNCH()   asm volatile("griddepcontrol.launch_dependents;")

__device__ __forceinline__ void store_hi2(f16* Ph, size_t idx, float2 v) {
    __half2 h = __floats2half2_rn(v.x, v.y);
    *(uint32_t*)(Ph + idx) = *(uint32_t*)&h;
}

// ---------------- raw mma helpers ----------------
__device__ __forceinline__ void ldsm4(uint32_t addr, uint32_t& r0, uint32_t& r1, uint32_t& r2, uint32_t& r3) {
    asm volatile("ldmatrix.sync.aligned.m8n8.x4.shared.b16 {%0,%1,%2,%3}, [%4];"
                 : "=r"(r0), "=r"(r1), "=r"(r2), "=r"(r3) : "r"(addr));
}
__device__ __forceinline__ void ldsm4t(uint32_t addr, uint32_t& r0, uint32_t& r1, uint32_t& r2, uint32_t& r3) {
    asm volatile("ldmatrix.sync.aligned.m8n8.x4.trans.shared.b16 {%0,%1,%2,%3}, [%4];"
                 : "=r"(r0), "=r"(r1), "=r"(r2), "=r"(r3) : "r"(addr));
}
__device__ __forceinline__ void mma16816(float* d, const uint32_t* a, const uint32_t* b) {
    asm volatile("mma.sync.aligned.m16n8k16.row.col.f32.f16.f16.f32 "
                 "{%0,%1,%2,%3}, {%4,%5,%6,%7}, {%8,%9}, {%0,%1,%2,%3};"
                 : "+f"(d[0]), "+f"(d[1]), "+f"(d[2]), "+f"(d[3])
                 : "r"(a[0]), "r"(a[1]), "r"(a[2]), "r"(a[3]), "r"(b[0]), "r"(b[1]));
}

// ---------------- GEMM: 128x128 tile, fp16, 4-stage cp.async, PDL ------
enum { EPI_T = 0, EPI_M, EPI_Z, EPI_R, EPI_GRU, EPI_R1 };

#define STAGES 4
#define LDA 40
#define LDB 136
#define A_OFF 0
#define B_OFF 10240
#define STAGE_BYTES 18944
#define SMEM_BYTES (STAGES*STAGE_BYTES)   // 75776 (x2 CTA/SM = 151552 <= 228KB)

// PRE_A/PRE_B: operand safe to prefetch before griddepcontrol.wait.
// TAILWAIT: no data dep on predecessor; wait only at kernel end.
template<int EPI, bool PRE_A, bool PRE_B, bool TAILWAIT>
__global__ void __launch_bounds__(256, 2)
tc_gemm(const f16* __restrict__ A0, const f16* __restrict__ A1,
        const f16* __restrict__ B,
        int NB, int K, int batched,
        const float* __restrict__ bias,
        const float* __restrict__ jc,
        const float* __restrict__ Hb,  const float* __restrict__ Zb,
        float* Cf, f16* Ch)
{
    extern __shared__ char sm[];
    const uint32_t smaddr = smem_u32(sm);

    const int tid = threadIdx.x, wid = tid >> 5, lane = tid & 31;
    const int bn = blockIdx.x * 128, bm = blockIdx.y * 128;
    const int warp_m = wid >> 2;
    const int warp_n = wid & 3;

    int am = bm;
    size_t aoff = 0, boff = 0;
    if (batched) {
        const int b = bm >> 8;
        aoff = (size_t)b * (Nn * Hn);
        boff = (size_t)b * (Nn * Hn);
        am = bm & (Nn - 1);
    }

    const int NC = K >> 5;

    auto issueA = [&](int kb) {
        const uint32_t sb = smaddr + (kb % STAGES) * STAGE_BYTES;
        const int kk = (kb & 7) * 32;
        const f16* ap; int arow;
        if (kb < 8) { ap = A0 + aoff; arow = am; }
        else        { ap = A1;        arow = bm; }
        #pragma unroll
        for (int i = 0; i < 2; i++) {
            const int c = tid + i * 256;
            const int r = c >> 2, c8 = (c & 3) * 8;
            CP16(sb + A_OFF + (uint32_t)(r * LDA + c8) * 2,
                 ap + (size_t)(arow + r) * Hn + kk + c8);
        }
    };
    auto issueB = [&](int kb) {
        const uint32_t sb = smaddr + (kb % STAGES) * STAGE_BYTES;
        #pragma unroll
        for (int i = 0; i < 2; i++) {
            const int c = tid + i * 256;
            const int r = c >> 4, c8 = (c & 15) * 8;
            CP16(sb + B_OFF + (uint32_t)(r * LDB + c8) * 2,
                 B + boff + (size_t)(kb * 32 + r) * NB + bn + c8);
        }
    };

    float acc[4][4][4];
    #pragma unroll
    for (int mi = 0; mi < 4; mi++)
        #pragma unroll
        for (int nj = 0; nj < 4; nj++)
            #pragma unroll
            for (int q = 0; q < 4; q++) acc[mi][nj][q] = 0.0f;

    const uint32_t a_lrow = (uint32_t)(lane & 15);
    const uint32_t a_lcol = (uint32_t)((lane >> 4) << 3);

    // -------- PDL-aware 4-stage prologue: chunks 0..S-2 --------
    if (PRE_A) { issueA(0); issueA(1); issueA(2); }
    if (PRE_B) { issueB(0); issueB(1); issueB(2); }
    CP_COMMIT();                        // group P (pre-wait loads)
    if (!TAILWAIT) GDC_WAIT();
    GDC_LAUNCH();
    #pragma unroll
    for (int c = 0; c < STAGES - 1; c++) {
        if (!PRE_A) issueA(c);
        if (!PRE_B) issueB(c);
        CP_COMMIT();
    }

    for (int kb = 0; kb < NC; kb++) {
        CP_WAIT(2);                     // chunk kb fully landed
        __syncthreads();

        if (kb + STAGES - 1 < NC) { issueA(kb + STAGES - 1); issueB(kb + STAGES - 1); }
        CP_COMMIT();

        const uint32_t sb = smaddr + (kb % STAGES) * STAGE_BYTES;

        #pragma unroll
        for (int kk = 0; kk < 2; kk++) {
            const uint32_t brow = (uint32_t)(kk * 16) + a_lrow;
            const uint32_t bcol0 = (uint32_t)(warp_n * 32) + a_lcol;
            uint32_t bfr[8];
            {
                const uint32_t ba = sb + B_OFF + (brow * LDB + bcol0) * 2;
                ldsm4t(ba,      bfr[0], bfr[1], bfr[2], bfr[3]);
                ldsm4t(ba + 32, bfr[4], bfr[5], bfr[6], bfr[7]);
            }
            const uint32_t arow0 = (uint32_t)(warp_m * 64) + a_lrow;
            const uint32_t acol = (uint32_t)(kk * 16) + a_lcol;
            #pragma unroll
            for (int mi = 0; mi < 4; mi++) {
                uint32_t a[4];
                ldsm4(sb + A_OFF + ((arow0 + mi * 16) * LDA + acol) * 2, a[0], a[1], a[2], a[3]);
                #pragma unroll
                for (int nj = 0; nj < 4; nj++) mma16816(acc[mi][nj], a, &bfr[nj * 2]);
            }
        }
    }

    // ---------------- register-direct epilogue ----------------
    const int r_in = lane >> 2;
    const int c_in = (lane & 3) * 2;

    #pragma unroll
    for (int mi = 0; mi < 4; mi++) {
        #pragma unroll
        for (int nj = 0; nj < 4; nj++) {
            #pragma unroll
            for (int half = 0; half < 2; half++) {
                const int row = bm + warp_m * 64 + mi * 16 + r_in + half * 8;
                const int col = bn + warp_n * 32 + nj * 8 + c_in;
                float2 v = make_float2(acc[mi][nj][half * 2], acc[mi][nj][half * 2 + 1]);
                const size_t idx = (size_t)row * Hn + col;

                if (EPI == EPI_T) {
                    float2 bv = *(const float2*)(bias + col);
                    v.x += bv.x; v.y += bv.y;
                    store_hi2(Ch, idx, v);
                } else if (EPI == EPI_M) {
                    v.x = tanhf(v.x); v.y = tanhf(v.y);
                    store_hi2(Ch, idx, v);
                } else if (EPI == EPI_Z) {
                    float2 jv = *(const float2*)(jc + idx);
                    v.x = sigf(v.x + jv.x); v.y = sigf(v.y + jv.y);
                    *(float2*)(Cf + idx) = v;
                } else if (EPI == EPI_R) {
                    float2 jv = *(const float2*)(jc + idx);
                    float2 hv = *(const float2*)(Hb + idx);
                    v.x = sigf(v.x + jv.x) * hv.x;
                    v.y = sigf(v.y + jv.y) * hv.y;
                    store_hi2(Ch, idx, v);
                } else if (EPI == EPI_GRU) {
                    float2 jv = *(const float2*)(jc + idx);
                    float2 hv = *(const float2*)(Hb + idx);
                    float2 zv = *(const float2*)(Zb + idx);
                    float t0 = tanhf(v.x + jv.x), t1 = tanhf(v.y + jv.y);
                    v.x = hv.x + zv.x * (t0 - hv.x);
                    v.y = hv.y + zv.y * (t1 - hv.y);
                    *(float2*)(Cf + idx) = v;
                    store_hi2(Ch, idx, v);
                } else if (EPI == EPI_R1) {
                    float2 bv = *(const float2*)(bias + col);
                    v.x = tanhf(v.x + bv.x); v.y = tanhf(v.y + bv.y);
                    *(float2*)(Cf + idx) = v;
                }
            }
        }
    }

    if (TAILWAIT) GDC_WAIT();
}

// ---------------- prep kernels ----------------
__global__ void cvt_hi(const float* __restrict__ src, int n4, f16* __restrict__ hi)
{
    const int i = blockIdx.x * 256 + threadIdx.x;
    if (i < n4) {
        float4 v = *(const float4*)(src + i * 4);
        __half2 h01 = __floats2half2_rn(v.x, v.y);
        __half2 h23 = __floats2half2_rn(v.z, v.w);
        uint2 hv; hv.x = *(uint32_t*)&h01; hv.y = *(uint32_t*)&h23;
        *(uint2*)(hi + (size_t)i * 4) = hv;
    }
}

__global__ void build_zrB(const float* __restrict__ Wz, const float* __restrict__ Wr,
                          const float* __restrict__ Uz, const float* __restrict__ Ur,
                          f16* __restrict__ hi)
{
    const int i = blockIdx.x * 256 + threadIdx.x;
    const int k = i >> 9, c = i & 511;
    float v;
    if (k < 256) v = (c < 256) ? Wz[k * Hn + c] : Wr[k * Hn + (c - 256)];
    else         v = (c < 256) ? Uz[(k - 256) * Hn + c] : Ur[(k - 256) * Hn + (c - 256)];
    hi[i] = __float2half_rn(v);
}

__global__ void build_hB(const float* __restrict__ Wh, const float* __restrict__ Uh,
                         f16* __restrict__ hi)
{
    const int i = blockIdx.x * 256 + threadIdx.x;
    const int k = i >> 8, c = i & 255;
    float v = (k < 256) ? Wh[k * Hn + c] : Uh[(k - 256) * Hn + c];
    hi[i] = __float2half_rn(v);
}

__global__ void emb_kernel(const float* __restrict__ jets, const float* __restrict__ W_emb,
                           const float* __restrict__ b_emb, float* __restrict__ h,
                           f16* __restrict__ hPh)
{
    const int row = blockIdx.x, j = threadIdx.x;
    __shared__ float sj[Fn];
    if (j < Fn) sj[j] = jets[(size_t)row * Fn + j];
    __syncthreads();
    float acc = b_emb[j];
    #pragma unroll
    for (int k = 0; k < Fn; k++) acc = fmaf(sj[k], W_emb[k * Hn + j], acc);
    const float v = tanhf(acc);
    const size_t idx = (size_t)row * Hn + j;
    h[idx] = v;
    hPh[idx] = __float2half_rn(v);
}

__global__ void jc_kernel(const float* __restrict__ jets,
                          const float* __restrict__ Wz, const float* __restrict__ Wr,
                          const float* __restrict__ Wh,
                          const float* __restrict__ bz, const float* __restrict__ br,
                          const float* __restrict__ bh,
                          float* jcz, float* jcr, float* jch)
{
    const int row = blockIdx.x, j = threadIdx.x;
    __shared__ float sj[Fn];
    if (j < Fn) sj[j] = jets[(size_t)row * Fn + j];
    __syncthreads();
    float az = bz[j], ar = br[j], ah = bh[j];
    #pragma unroll
    for (int k = 0; k < Fn; k++) {
        const float s = sj[k];
        const int widx = (Hn + k) * Hn + j;
        az = fmaf(s, Wz[widx], az);
        ar = fmaf(s, Wr[widx], ar);
        ah = fmaf(s, Wh[widx], ah);
    }
    const size_t idx = (size_t)row * Hn + j;
    jcz[idx] = az; jcr[idx] = ar; jch[idx] = ah;
}

__global__ void reduce_kernel(const float* __restrict__ t1, float* __restrict__ s)
{
    const int idx = blockIdx.x * blockDim.x + threadIdx.x;
    const int b = idx >> 8, j = idx & 255;
    const float* p = t1 + (size_t)b * (Nn * Hn) + j;
    float acc = 0.0f;
    for (int n = 0; n < Nn; n++) acc += p[(size_t)n * Hn];
    s[idx] = acc;
}

__global__ void readout_kernel(const float* __restrict__ s, const float* __restrict__ W_r2,
                               const float* __restrict__ b_r2, float* __restrict__ out)
{
    const int b = blockIdx.x, j = threadIdx.x;
    __shared__ float sr[Hn];
    sr[j] = s[(size_t)b * Hn + j];
    __syncthreads();
    float acc = (float)Nn * b_r2[j];
    #pragma unroll 8
    for (int k = 0; k < Hn; k++)
        acc = fmaf(sr[k], W_r2[k * Hn + j], acc);
    out[(size_t)b * Hn + j] = acc;
}

// ---------------- launch ----------------
template<typename KF, typename... Args>
static inline void pdl_launch(KF kern, dim3 grid, Args... args)
{
    cudaLaunchConfig_t cfg = {};
    cfg.gridDim = grid;
    cfg.blockDim = dim3(256, 1, 1);
    cfg.dynamicSmemBytes = SMEM_BYTES;
    cfg.stream = 0;
    cudaLaunchAttribute at[1];
    at[0].id = cudaLaunchAttributeProgrammaticStreamSerialization;
    at[0].val.programmaticStreamSerializationAllowed = 1;
    cfg.attrs = at;
    cfg.numAttrs = 1;
    cudaLaunchKernelEx(&cfg, kern, args...);
}

extern "C" void kernel_launch(void* const* d_in, const int* in_sizes, int n_in,
                              void* d_out, int out_size)
{
    const float* jets  = (const float*)d_in[0];
    const float* dads  = (const float*)d_in[1];
    const float* W_emb = (const float*)d_in[2];
    const float* b_emb = (const float*)d_in[3];
    const float* W_msg = (const float*)d_in[4];
    const float* b_msg = (const float*)d_in[5];
    const float* Wz    = (const float*)d_in[6];
    const float* Uz    = (const float*)d_in[7];
    const float* bz    = (const float*)d_in[8];
    const float* Wr    = (const float*)d_in[9];
    const float* Ur    = (const float*)d_in[10];
    const float* br    = (const float*)d_in[11];
    const float* Wh    = (const float*)d_in[12];
    const float* Uh    = (const float*)d_in[13];
    const float* bh    = (const float*)d_in[14];
    const float* W_r1  = (const float*)d_in[15];
    const float* b_r1  = (const float*)d_in[16];
    const float* W_r2  = (const float*)d_in[17];
    const float* b_r2  = (const float*)d_in[18];
    float* out = (float*)d_out;

    float *h, *z, *jcz, *jcr, *jch, *t1, *s;
    f16 *hP, *tP, *mP, *rhP, *daP, *wH;
    cudaGetSymbolAddress((void**)&h,   g_h);
    cudaGetSymbolAddress((void**)&z,   g_z);
    cudaGetSymbolAddress((void**)&jcz, g_jcz);
    cudaGetSymbolAddress((void**)&jcr, g_jcr);
    cudaGetSymbolAddress((void**)&jch, g_jch);
    cudaGetSymbolAddress((void**)&t1,  g_t1);
    cudaGetSymbolAddress((void**)&s,   g_s);
    cudaGetSymbolAddress((void**)&hP,  g_hP);
    cudaGetSymbolAddress((void**)&tP,  g_tP);
    cudaGetSymbolAddress((void**)&mP,  g_mP);
    cudaGetSymbolAddress((void**)&rhP, g_rhP);
    cudaGetSymbolAddress((void**)&daP, g_daP);
    cudaGetSymbolAddress((void**)&wH,  g_wH);

    static bool attr_done = false;
    if (!attr_done) {
        cudaFuncSetAttribute(tc_gemm<EPI_T,false,true,false>,  cudaFuncAttributeMaxDynamicSharedMemorySize, SMEM_BYTES);
        cudaFuncSetAttribute(tc_gemm<EPI_M,true,false,false>,  cudaFuncAttributeMaxDynamicSharedMemorySize, SMEM_BYTES);
        cudaFuncSetAttribute(tc_gemm<EPI_Z,false,true,false>,  cudaFuncAttributeMaxDynamicSharedMemorySize, SMEM_BYTES);
        cudaFuncSetAttribute(tc_gemm<EPI_R,true,true,true>,    cudaFuncAttributeMaxDynamicSharedMemorySize, SMEM_BYTES);
        cudaFuncSetAttribute(tc_gemm<EPI_GRU,true,true,false>, cudaFuncAttributeMaxDynamicSharedMemorySize, SMEM_BYTES);
        cudaFuncSetAttribute(tc_gemm<EPI_R1,false,true,false>, cudaFuncAttributeMaxDynamicSharedMemorySize, SMEM_BYTES);
        attr_done = true;
    }

    // prep
    cvt_hi<<<PLANE/4/256, 256>>>(dads, PLANE/4, daP);
    cvt_hi<<<65536/4/256, 256>>>(W_msg, 65536/4, wH + WOFF_MSG);
    cvt_hi<<<65536/4/256, 256>>>(W_r1,  65536/4, wH + WOFF_R1);
    build_zrB<<<262144/256, 256>>>(Wz, Wr, Uz, Ur, wH + WOFF_ZR);
    build_hB<<<131072/256, 256>>>(Wh, Uh, wH + WOFF_HB);
    emb_kernel<<<ROWS, Hn>>>(jets, W_emb, b_emb, h, hP);
    jc_kernel<<<ROWS, Hn>>>(jets, Wz, Wr, Wh, bz, br, bh, jcz, jcr, jch);

    dim3 grid2(2, ROWS/128);   // every GEMM: 256 CTAs = one full wave at 2 CTA/SM
    for (int it = 0; it < N_ITERS; it++) {
        // t = h @ W_msg + b_msg          (A=hP dep; B weights pre)
        pdl_launch(tc_gemm<EPI_T,false,true,false>, grid2,
            hP, (const f16*)nullptr, (const f16*)(wH + WOFF_MSG), 256, 256, 0,
            b_msg, (const float*)nullptr, (const float*)nullptr, (const float*)nullptr,
            (float*)nullptr, tP);
        // m = tanh(dads @ t)             (A=daP const pre; B=tP dep)
        pdl_launch(tc_gemm<EPI_M,true,false,false>, grid2,
            daP, (const f16*)nullptr, tP, 256, 256, 1,
            (const float*)nullptr, (const float*)nullptr, (const float*)nullptr, (const float*)nullptr,
            (float*)nullptr, mP);
        // z = sigmoid([m|h]@[Wz;Uz]+jcz) (A=mP dep; B weights pre)
        pdl_launch(tc_gemm<EPI_Z,false,true,false>, grid2,
            mP, hP, (const f16*)(wH + WOFF_ZR), 512, 512, 0,
            (const float*)nullptr, jcz, (const float*)nullptr, (const float*)nullptr,
            z, (f16*)nullptr);
        // rh = sigmoid([m|h]@[Wr;Ur]+jcr)*h  (no dep on Z: prefetch all, wait at END)
        pdl_launch(tc_gemm<EPI_R,true,true,true>, grid2,
            mP, hP, (const f16*)(wH + WOFF_ZR + 256), 512, 512, 0,
            (const float*)nullptr, jcr, h, (const float*)nullptr,
            (float*)nullptr, rhP);
        // h = (1-z)*h + z*tanh([m|rh]@[Wh;Uh]+jch)
        pdl_launch(tc_gemm<EPI_GRU,true,true,false>, grid2,
            mP, rhP, (const f16*)(wH + WOFF_HB), 256, 512, 0,
            (const float*)nullptr, jch, h, z,
            h, hP);
    }

    // readout
    pdl_launch(tc_gemm<EPI_R1,false,true,false>, grid2,
        hP, (const f16*)nullptr, (const f16*)(wH + WOFF_R1), 256, 256, 0,
        b_r1, (const float*)nullptr, (const float*)nullptr, (const float*)nullptr,
        t1, (f16*)nullptr);
    reduce_kernel<<<ROWS/256, 256>>>(t1, s);
    readout_kernel<<<Bn, Hn>>>(s, W_r2, b_r2, out);
}